// round 8
// baseline (speedup 1.0000x reference)
#include <cuda_runtime.h>
#include <math.h>
#include <stdint.h>

#define TT 262144
#define S 128
#define F 16
#define CH 296
#define L 886           // 296 * 886 = 262256 >= TT
#define W 128           // warmup steps (forgetting window)
#define NZ 4            // renormalize every NZ steps

// ---------------- scratch (device globals; no allocation allowed) ----------------
__device__ float g_expB[(size_t)TT * S];       // exp(logB - mB) per row, 134 MB
__device__ float g_mB[TT];                     // per-row max of logB
__device__ float g_E[S * S];                   // row-stochastic softmax(trans)
__device__ float g_pstart[S];                  // exp(log_softmax(start))
__device__ float g_iv[S * F];
__device__ float g_m2[S * F];
__device__ float g_cst[S];
__device__ float g_junc[CH * S];               // linear junction vectors
__device__ float g_joff[CH];                   // offsets at junctions
__device__ float g_rl[TT];                     // per-row accumulated offset (chunk frame)
__device__ float g_dloc[CH];
__device__ float g_delta[CH];

// ---------------- fast math (FMA polys; no MUFU) ----------------
__device__ __forceinline__ float fexp_poly(float x) {
    x = fmaxf(x, -80.0f);
    float y = x * 1.44269504f;
    float n = rintf(y);
    float t = (y - n) * 0.69314718f;
    float p = 1.0f / 720.0f;
    p = fmaf(p, t, 1.0f / 120.0f);
    p = fmaf(p, t, 1.0f / 24.0f);
    p = fmaf(p, t, 1.0f / 6.0f);
    p = fmaf(p, t, 0.5f);
    p = fmaf(p, t, 1.0f);
    p = fmaf(p, t, 1.0f);
    return p * __int_as_float(((int)n + 127) << 23);
}

__device__ __forceinline__ float flog_poly(float v) {
    v = fmaxf(v, 1e-38f);
    int b = __float_as_int(v);
    int e = ((b >> 23) & 255) - 127;
    float m = __int_as_float((b & 0x007fffff) | 0x3f800000);  // [1,2)
    if (m > 1.41421356f) { m *= 0.5f; e += 1; }
    float r = m - 1.0f;
    float p = -1.0f / 12.0f;
    p = fmaf(p, r,  1.0f / 11.0f);
    p = fmaf(p, r, -1.0f / 10.0f);
    p = fmaf(p, r,  1.0f / 9.0f);
    p = fmaf(p, r, -1.0f / 8.0f);
    p = fmaf(p, r,  1.0f / 7.0f);
    p = fmaf(p, r, -1.0f / 6.0f);
    p = fmaf(p, r,  1.0f / 5.0f);
    p = fmaf(p, r, -0.25f);
    p = fmaf(p, r,  1.0f / 3.0f);
    p = fmaf(p, r, -0.5f);
    p = fmaf(p, r,  1.0f);
    return fmaf((float)e, 0.69314718f, r * p);
}

// ---------------- kernel 1: small preprocessing ----------------
__global__ void prep_kernel(const float* __restrict__ start_prob,
                            const float* __restrict__ trans,
                            const float* __restrict__ means,
                            const float* __restrict__ vars) {
    int s = threadIdx.x;  // 128 threads
    __shared__ float red[S];

    float sp = start_prob[s];
    red[s] = sp; __syncthreads();
    for (int o = 64; o > 0; o >>= 1) { if (s < o) red[s] = fmaxf(red[s], red[s + o]); __syncthreads(); }
    float mx = red[0]; __syncthreads();
    red[s] = expf(sp - mx); __syncthreads();
    for (int o = 64; o > 0; o >>= 1) { if (s < o) red[s] += red[s + o]; __syncthreads(); }
    float lse = mx + logf(red[0]);
    g_pstart[s] = expf(sp - lse);

    float m = -INFINITY;
    for (int j = 0; j < S; j++) m = fmaxf(m, trans[s * S + j]);
    float z = 0.f;
    for (int j = 0; j < S; j++) z += expf(trans[s * S + j] - m);
    float inv = 1.0f / z;
    for (int j = 0; j < S; j++) g_E[s * S + j] = expf(trans[s * S + j] - m) * inv;

    float ln = 0.f, c2 = 0.f;
    for (int f = 0; f < F; f++) {
        float v = vars[s * F + f];
        v = fmaxf(v, 1e-6f);
        float iv = 1.0f / v;
        float mu = means[s * F + f];
        g_iv[s * F + f] = iv;
        g_m2[s * F + f] = 2.0f * mu * iv;
        ln += logf(6.2831853071795864f * v);
        c2 += mu * mu * iv;
    }
    g_cst[s] = -0.5f * (ln + c2);
}

// ---------------- kernel 2: emissions -> expB + mB ----------------
#define LB_STRIDE 130
__global__ void logb_kernel(const float* __restrict__ x) {
    int s = threadIdx.x;             // 128 threads (= states)
    int t0 = blockIdx.x * 64;        // 64 timesteps per block
    __shared__ float sx[64 * F];
    __shared__ float slb[64 * LB_STRIDE];
    __shared__ float smB[64];

    for (int i = s; i < 64 * F; i += S) sx[i] = x[(size_t)t0 * F + i];
    float iv[F], m2[F];
#pragma unroll
    for (int f = 0; f < F; f++) { iv[f] = g_iv[s * F + f]; m2[f] = g_m2[s * F + f]; }
    float cst = g_cst[s];
    __syncthreads();

    for (int t = 0; t < 64; t++) {
        float q = 0.f;
#pragma unroll
        for (int f = 0; f < F; f++) {
            float xv = sx[t * F + f];
            q = fmaf(xv, fmaf(xv, iv[f], -m2[f]), q);
        }
        slb[t * LB_STRIDE + s] = cst - 0.5f * q;
    }
    __syncthreads();

    {
        int t = s >> 1, half = s & 1;
        float mx = -INFINITY;
        const float* row = slb + t * LB_STRIDE + half * 64;
        for (int i = 0; i < 64; i++) mx = fmaxf(mx, row[i]);
        mx = fmaxf(mx, __shfl_xor_sync(0xffffffffu, mx, 1));
        if (half == 0) { smB[t] = mx; g_mB[t0 + t] = mx; }
    }
    __syncthreads();

    for (int t = 0; t < 64; t++) {
        float eb = fexp_poly(slb[t * LB_STRIDE + s] - smB[t]);
        g_expB[(size_t)(t0 + t) * S + s] = eb;
    }
}

// ---------------- kernel 3: linear-domain scan, 1 barrier/step ----------------
// Warp w owns columns [w*16, w*16+16); lane l = (col offset)<<1 | half.
// Thread holds E[half*64 + k][j] for k = 0..63 in registers.
// sw double-buffered: iteration `it` publishes & reads swb[it & 1].
__global__ void __launch_bounds__(256, 2) scan_kernel(float* __restrict__ out) {
    __shared__ float swb[2][S];
    __shared__ float wmax[8];

    int tid = threadIdx.x;
    int w = tid >> 5, l = tid & 31;
    int j = w * 16 + (l >> 1);
    int half = l & 1;
    int c = blockIdx.x;

    float e[64];
#pragma unroll
    for (int k = 0; k < 64; k++) e[k] = g_E[(half * 64 + k) * S + j];

    long wstart = (long)c * L;
    long wend = wstart + L; if (wend > TT) wend = TT;
    long t0 = (c == 0) ? 0 : (wstart - W);
    long tstop = (c < CH - 1) ? (wstart + L + 1) : wend;

    float v, off;
    if (c == 0) {
        v = g_pstart[j] * g_expB[j];
        off = g_mB[0];
        if (half == 0) { out[j] = v; if (tid == 0) g_rl[0] = off; }
    } else {
        v = g_expB[(size_t)t0 * S + j];   // arbitrary positive start; forgotten in W steps
        off = g_mB[t0];
    }

    float eb = g_expB[(size_t)(t0 + 1) * S + j];
    float mb = g_mB[t0 + 1];

    int it = 0;
    for (long t = t0 + 1; t < tstop; t++, it++) {
        float* sw = swb[it & 1];
        bool rn = (it & (NZ - 1)) == 0;

        if (half == 0) sw[j] = v;           // publish current vector
        if (rn) {
            float u = v;
#pragma unroll
            for (int o = 16; o > 0; o >>= 1) u = fmaxf(u, __shfl_xor_sync(0xffffffffu, u, o));
            if (l == 0) wmax[w] = u;
        }
        __syncthreads();                    // the ONLY barrier per step

        float invM = 1.0f, logM = 0.0f;
        if (rn) {
            float M = wmax[0];
#pragma unroll
            for (int q = 1; q < 8; q++) M = fmaxf(M, wmax[q]);
            invM = 1.0f / M;
            logM = __logf(M);
        }

        // dot over my 64 rows (sw reads: 2 distinct 16B lines per LDS.128 -> conflict-free)
        const float4* s4 = (const float4*)(sw + half * 64);
        float p0 = 0.f, p1 = 0.f, p2 = 0.f, p3 = 0.f;
#pragma unroll
        for (int k = 0; k < 16; k++) {
            float4 q4 = s4[k];
            p0 = fmaf(q4.x, e[4 * k],     p0);
            p1 = fmaf(q4.y, e[4 * k + 1], p1);
            p2 = fmaf(q4.z, e[4 * k + 2], p2);
            p3 = fmaf(q4.w, e[4 * k + 3], p3);
        }
        float p = (p0 + p1) + (p2 + p3);
        p += __shfl_xor_sync(0xffffffffu, p, 1);   // pair-reduce: full 128-sum in both lanes

        v = p * eb * invM;
        off += mb + logM;

        // prefetch next emission row
        if (t + 1 < tstop) {
            eb = g_expB[(size_t)(t + 1) * S + j];
            mb = g_mB[t + 1];
        }

        if (half == 0) {
            if (t >= wstart && t < wend) {
                out[(size_t)t * S + j] = v;        // LINEAR; converted in post pass
                if (tid == 0) g_rl[t] = off;
            } else if (t == wstart + L) {
                g_junc[(c + 1) * S + j] = v;
                if (tid == 0) g_joff[c + 1] = off;
            }
        }
    }
}

// ---------------- kernel 4a: per-junction offsets (linear lse diff) ----------------
__global__ void delta_local_kernel(const float* __restrict__ out) {
    int c = blockIdx.x + 1;          // 1..CH-1
    int j = threadIdx.x;             // 128
    __shared__ float s4[8];

    float jv = g_junc[c * S + j];
    float ov = out[(size_t)c * L * S + j];

    float z = jv;
#pragma unroll
    for (int o = 16; o > 0; o >>= 1) z += __shfl_xor_sync(0xffffffffu, z, o);
    if ((j & 31) == 0) s4[j >> 5] = z;
    __syncthreads();
    float sum1 = s4[0] + s4[1] + s4[2] + s4[3];
    __syncthreads();

    z = ov;
#pragma unroll
    for (int o = 16; o > 0; o >>= 1) z += __shfl_xor_sync(0xffffffffu, z, o);
    if ((j & 31) == 0) s4[j >> 5] = z;
    __syncthreads();
    float sum2 = s4[0] + s4[1] + s4[2] + s4[3];

    if (j == 0)
        g_dloc[c] = (g_joff[c] + __logf(sum1)) - (g_rl[(size_t)c * L] + __logf(sum2));
}

// ---------------- kernel 4b: tiny prefix scan ----------------
__global__ void delta_scan_kernel() {
    if (threadIdx.x == 0) {
        float d = 0.f;
        g_delta[0] = 0.f;
        for (int c = 1; c < CH; c++) { d += g_dloc[c]; g_delta[c] = d; }
    }
}

// ---------------- kernel 5: fused log + offset + delta ----------------
__global__ void post_kernel(float* __restrict__ out) {
    size_t n4 = (size_t)TT * S / 4;
    size_t i4 = (size_t)blockIdx.x * blockDim.x + threadIdx.x;
    if (i4 >= n4) return;
    size_t e = i4 * 4;
    size_t t = e / S;
    int c = (int)(t / L);
    float add = g_rl[t] + g_delta[c];
    float4* p = (float4*)(out + e);
    float4 v = *p;
    v.x = flog_poly(v.x) + add;
    v.y = flog_poly(v.y) + add;
    v.z = flog_poly(v.z) + add;
    v.w = flog_poly(v.w) + add;
    *p = v;
}

// ---------------- kernel 6: final log-likelihood ----------------
__global__ void ll_kernel(float* __restrict__ out, int out_size) {
    int lane = threadIdx.x;  // 32
    const float* last = out + (size_t)(TT - 1) * S;
    float v0 = last[lane], v1 = last[lane + 32], v2 = last[lane + 64], v3 = last[lane + 96];
    float m = fmaxf(fmaxf(v0, v1), fmaxf(v2, v3));
    for (int o = 16; o > 0; o >>= 1) m = fmaxf(m, __shfl_xor_sync(0xffffffffu, m, o));
    float s = __expf(v0 - m) + __expf(v1 - m) + __expf(v2 - m) + __expf(v3 - m);
    for (int o = 16; o > 0; o >>= 1) s += __shfl_xor_sync(0xffffffffu, s, o);
    if (lane == 0 && out_size > TT * S) out[(size_t)TT * S] = m + __logf(s);
}

// ---------------- launch ----------------
extern "C" void kernel_launch(void* const* d_in, const int* in_sizes, int n_in,
                              void* d_out, int out_size) {
    const float* x          = (const float*)d_in[0];
    const float* start_prob = (const float*)d_in[1];
    const float* trans      = (const float*)d_in[2];
    const float* means      = (const float*)d_in[3];
    const float* vars       = (const float*)d_in[4];
    float* out = (float*)d_out;

    prep_kernel<<<1, 128>>>(start_prob, trans, means, vars);
    logb_kernel<<<TT / 64, 128>>>(x);
    scan_kernel<<<CH, 256>>>(out);
    delta_local_kernel<<<CH - 1, 128>>>(out);
    delta_scan_kernel<<<1, 32>>>();
    size_t n4 = (size_t)TT * S / 4;
    post_kernel<<<(unsigned)((n4 + 255) / 256), 256>>>(out);
    ll_kernel<<<1, 32>>>(out, out_size);
}

// round 9
// speedup vs baseline: 1.2315x; 1.2315x over previous
#include <cuda_runtime.h>
#include <math.h>
#include <stdint.h>

#define TT 262144
#define S 128
#define F 16
#define CH 296
#define L 886           // 296 * 886 = 262256 >= TT
#define W 128           // warmup steps (forgetting window)
#define NZ 4            // renormalize every NZ steps
#define PF 16           // staged rows per block

// ---------------- scratch (device globals; no allocation allowed) ----------------
__device__ float g_expB[(size_t)TT * S];       // exp(logB - mB) per row, 134 MB
__device__ float g_mB[TT];                     // per-row max of logB
__device__ float g_E[S * S];                   // row-stochastic softmax(trans)
__device__ float g_pstart[S];                  // exp(log_softmax(start))
__device__ float g_iv[S * F];
__device__ float g_m2[S * F];
__device__ float g_cst[S];
__device__ float g_junc[CH * S];               // linear junction vectors
__device__ float g_joff[CH];                   // offsets at junctions
__device__ float g_rl[TT];                     // per-row accumulated offset (chunk frame)
__device__ float g_dloc[CH];
__device__ float g_delta[CH];

// ---------------- fast math (FMA polys; no MUFU) ----------------
__device__ __forceinline__ float fexp_poly(float x) {
    x = fmaxf(x, -80.0f);
    float y = x * 1.44269504f;
    float n = rintf(y);
    float t = (y - n) * 0.69314718f;
    float p = 1.0f / 720.0f;
    p = fmaf(p, t, 1.0f / 120.0f);
    p = fmaf(p, t, 1.0f / 24.0f);
    p = fmaf(p, t, 1.0f / 6.0f);
    p = fmaf(p, t, 0.5f);
    p = fmaf(p, t, 1.0f);
    p = fmaf(p, t, 1.0f);
    return p * __int_as_float(((int)n + 127) << 23);
}

__device__ __forceinline__ float flog_poly(float v) {
    v = fmaxf(v, 1e-38f);
    int b = __float_as_int(v);
    int e = ((b >> 23) & 255) - 127;
    float m = __int_as_float((b & 0x007fffff) | 0x3f800000);  // [1,2)
    if (m > 1.41421356f) { m *= 0.5f; e += 1; }
    float r = m - 1.0f;
    float p = -1.0f / 12.0f;
    p = fmaf(p, r,  1.0f / 11.0f);
    p = fmaf(p, r, -1.0f / 10.0f);
    p = fmaf(p, r,  1.0f / 9.0f);
    p = fmaf(p, r, -1.0f / 8.0f);
    p = fmaf(p, r,  1.0f / 7.0f);
    p = fmaf(p, r, -1.0f / 6.0f);
    p = fmaf(p, r,  1.0f / 5.0f);
    p = fmaf(p, r, -0.25f);
    p = fmaf(p, r,  1.0f / 3.0f);
    p = fmaf(p, r, -0.5f);
    p = fmaf(p, r,  1.0f);
    return fmaf((float)e, 0.69314718f, r * p);
}

// ---------------- kernel 1: small preprocessing ----------------
__global__ void prep_kernel(const float* __restrict__ start_prob,
                            const float* __restrict__ trans,
                            const float* __restrict__ means,
                            const float* __restrict__ vars) {
    int s = threadIdx.x;  // 128 threads
    __shared__ float red[S];

    float sp = start_prob[s];
    red[s] = sp; __syncthreads();
    for (int o = 64; o > 0; o >>= 1) { if (s < o) red[s] = fmaxf(red[s], red[s + o]); __syncthreads(); }
    float mx = red[0]; __syncthreads();
    red[s] = expf(sp - mx); __syncthreads();
    for (int o = 64; o > 0; o >>= 1) { if (s < o) red[s] += red[s + o]; __syncthreads(); }
    float lse = mx + logf(red[0]);
    g_pstart[s] = expf(sp - lse);

    float m = -INFINITY;
    for (int j = 0; j < S; j++) m = fmaxf(m, trans[s * S + j]);
    float z = 0.f;
    for (int j = 0; j < S; j++) z += expf(trans[s * S + j] - m);
    float inv = 1.0f / z;
    for (int j = 0; j < S; j++) g_E[s * S + j] = expf(trans[s * S + j] - m) * inv;

    float ln = 0.f, c2 = 0.f;
    for (int f = 0; f < F; f++) {
        float v = vars[s * F + f];
        v = fmaxf(v, 1e-6f);
        float iv = 1.0f / v;
        float mu = means[s * F + f];
        g_iv[s * F + f] = iv;
        g_m2[s * F + f] = 2.0f * mu * iv;
        ln += logf(6.2831853071795864f * v);
        c2 += mu * mu * iv;
    }
    g_cst[s] = -0.5f * (ln + c2);
}

// ---------------- kernel 2: emissions -> expB + mB ----------------
#define LB_STRIDE 130
__global__ void logb_kernel(const float* __restrict__ x) {
    int s = threadIdx.x;             // 128 threads (= states)
    int t0 = blockIdx.x * 64;        // 64 timesteps per block
    __shared__ float sx[64 * F];
    __shared__ float slb[64 * LB_STRIDE];
    __shared__ float smB[64];

    for (int i = s; i < 64 * F; i += S) sx[i] = x[(size_t)t0 * F + i];
    float iv[F], m2[F];
#pragma unroll
    for (int f = 0; f < F; f++) { iv[f] = g_iv[s * F + f]; m2[f] = g_m2[s * F + f]; }
    float cst = g_cst[s];
    __syncthreads();

    for (int t = 0; t < 64; t++) {
        float q = 0.f;
#pragma unroll
        for (int f = 0; f < F; f++) {
            float xv = sx[t * F + f];
            q = fmaf(xv, fmaf(xv, iv[f], -m2[f]), q);
        }
        slb[t * LB_STRIDE + s] = cst - 0.5f * q;
    }
    __syncthreads();

    {
        int t = s >> 1, half = s & 1;
        float mx = -INFINITY;
        const float* row = slb + t * LB_STRIDE + half * 64;
        for (int i = 0; i < 64; i++) mx = fmaxf(mx, row[i]);
        mx = fmaxf(mx, __shfl_xor_sync(0xffffffffu, mx, 1));
        if (half == 0) { smB[t] = mx; g_mB[t0 + t] = mx; }
    }
    __syncthreads();

    for (int t = 0; t < 64; t++) {
        float eb = fexp_poly(slb[t * LB_STRIDE + s] - smB[t]);
        g_expB[(size_t)(t0 + t) * S + s] = eb;
    }
}

// ---------------- kernel 3: linear scan, 1 barrier/step, smem-staged emissions --------
// Warp w owns columns [w*16, w*16+16); lane l = (col offset)<<1 | half.
// Thread holds E[half*64 + k][j] for k = 0..63 in registers.
// expB rows staged PF at a time: LDG at block start (distance PF), STS at block end.
__global__ void __launch_bounds__(256, 2) scan_kernel(float* __restrict__ out) {
    __shared__ float swb[2][S];
    __shared__ float sbuf[2][PF * S];
    __shared__ float smb[2][PF];
    __shared__ float wmax[8];

    int tid = threadIdx.x;
    int w = tid >> 5, l = tid & 31;
    int j = w * 16 + (l >> 1);
    int half = l & 1;
    int c = blockIdx.x;
    int srow = tid >> 4;              // staging row 0..15
    int scol = (tid & 15) * 8;        // staging col offset

    float e[64];
#pragma unroll
    for (int k = 0; k < 64; k++) e[k] = g_E[(half * 64 + k) * S + j];

    long wstart = (long)c * L;
    long wend = wstart + L; if (wend > TT) wend = TT;
    long t0 = (c == 0) ? 0 : (wstart - W);
    long tstop = (c < CH - 1) ? (wstart + L + 1) : wend;
    long tbase = t0 + 1;
    int niter = (int)(tstop - tbase);

    float v, off;
    if (c == 0) {
        v = g_pstart[j] * g_expB[j];
        off = g_mB[0];
        if (half == 0) { out[j] = v; if (tid == 0) g_rl[0] = off; }
    } else {
        v = g_expB[(size_t)t0 * S + j];   // arbitrary positive start; forgotten in W steps
        off = g_mB[t0];
    }

    // preload staging block 0
    {
        long tt = tbase + srow; if (tt > TT - 1) tt = TT - 1;
        const float4* src = (const float4*)&g_expB[tt * S + scol];
        float4 a0 = src[0], a1 = src[1];
        ((float4*)&sbuf[0][srow * S + scol])[0] = a0;
        ((float4*)&sbuf[0][srow * S + scol])[1] = a1;
        if (tid < PF) {
            long t2 = tbase + tid; if (t2 > TT - 1) t2 = TT - 1;
            smb[0][tid] = g_mB[t2];
        }
    }
    __syncthreads();

    float4 r0, r1;            // staged registers for next block
    float rmb = 0.f;

    for (int it = 0; it < niter; it++) {
        long t = tbase + it;
        int blk = it >> 4;
        int phase = it & 15;
        float* sw = swb[it & 1];
        bool rn = (it & (NZ - 1)) == 0;

        if (half == 0) sw[j] = v;           // publish current vector
        if (phase == 15) {                  // commit staged block blk+1
            ((float4*)&sbuf[(blk + 1) & 1][srow * S + scol])[0] = r0;
            ((float4*)&sbuf[(blk + 1) & 1][srow * S + scol])[1] = r1;
            if (tid < PF) smb[(blk + 1) & 1][tid] = rmb;
        }
        if (rn) {
            float u = v;
#pragma unroll
            for (int o = 16; o > 0; o >>= 1) u = fmaxf(u, __shfl_xor_sync(0xffffffffu, u, o));
            if (l == 0) wmax[w] = u;
        }
        __syncthreads();                    // the ONLY barrier per step

        if (phase == 0) {                   // issue LDG for block blk+1 (15-step lead)
            long tt = tbase + (long)(blk + 1) * PF + srow;
            if (tt > TT - 1) tt = TT - 1;
            const float4* src = (const float4*)&g_expB[tt * S + scol];
            r0 = src[0]; r1 = src[1];
            if (tid < PF) {
                long t2 = tbase + (long)(blk + 1) * PF + tid;
                if (t2 > TT - 1) t2 = TT - 1;
                rmb = g_mB[t2];
            }
        }

        float invM = 1.0f, logM = 0.0f;
        if (rn) {
            float M = wmax[0];
#pragma unroll
            for (int q = 1; q < 8; q++) M = fmaxf(M, wmax[q]);
            invM = 1.0f / M;
            logM = __logf(M);
        }

        float eb = sbuf[blk & 1][phase * S + j];
        float mb = smb[blk & 1][phase];

        // dot over my 64 rows
        const float4* s4 = (const float4*)(sw + half * 64);
        float p0 = 0.f, p1 = 0.f, p2 = 0.f, p3 = 0.f;
#pragma unroll
        for (int k = 0; k < 16; k++) {
            float4 q4 = s4[k];
            p0 = fmaf(q4.x, e[4 * k],     p0);
            p1 = fmaf(q4.y, e[4 * k + 1], p1);
            p2 = fmaf(q4.z, e[4 * k + 2], p2);
            p3 = fmaf(q4.w, e[4 * k + 3], p3);
        }
        float p = (p0 + p1) + (p2 + p3);
        p += __shfl_xor_sync(0xffffffffu, p, 1);   // full 128-sum in both lanes

        v = p * eb * invM;
        off += mb + logM;

        if (half == 0) {
            if (t >= wstart && t < wend) {
                out[(size_t)t * S + j] = v;        // LINEAR; converted in post pass
                if (tid == 0) g_rl[t] = off;
            } else if (t == wstart + L) {
                g_junc[(c + 1) * S + j] = v;
                if (tid == 0) g_joff[c + 1] = off;
            }
        }
    }
}

// ---------------- kernel 4a: per-junction offsets (linear lse diff) ----------------
__global__ void delta_local_kernel(const float* __restrict__ out) {
    int c = blockIdx.x + 1;          // 1..CH-1
    int j = threadIdx.x;             // 128
    __shared__ float s4[8];

    float jv = g_junc[c * S + j];
    float ov = out[(size_t)c * L * S + j];

    float z = jv;
#pragma unroll
    for (int o = 16; o > 0; o >>= 1) z += __shfl_xor_sync(0xffffffffu, z, o);
    if ((j & 31) == 0) s4[j >> 5] = z;
    __syncthreads();
    float sum1 = s4[0] + s4[1] + s4[2] + s4[3];
    __syncthreads();

    z = ov;
#pragma unroll
    for (int o = 16; o > 0; o >>= 1) z += __shfl_xor_sync(0xffffffffu, z, o);
    if ((j & 31) == 0) s4[j >> 5] = z;
    __syncthreads();
    float sum2 = s4[0] + s4[1] + s4[2] + s4[3];

    if (j == 0)
        g_dloc[c] = (g_joff[c] + __logf(sum1)) - (g_rl[(size_t)c * L] + __logf(sum2));
}

// ---------------- kernel 4b: tiny prefix scan ----------------
__global__ void delta_scan_kernel() {
    if (threadIdx.x == 0) {
        float d = 0.f;
        g_delta[0] = 0.f;
        for (int c = 1; c < CH; c++) { d += g_dloc[c]; g_delta[c] = d; }
    }
}

// ---------------- kernel 5: fused log + offset + delta ----------------
__global__ void post_kernel(float* __restrict__ out) {
    size_t n4 = (size_t)TT * S / 4;
    size_t i4 = (size_t)blockIdx.x * blockDim.x + threadIdx.x;
    if (i4 >= n4) return;
    size_t e = i4 * 4;
    size_t t = e / S;
    int c = (int)(t / L);
    float add = g_rl[t] + g_delta[c];
    float4* p = (float4*)(out + e);
    float4 v = *p;
    v.x = flog_poly(v.x) + add;
    v.y = flog_poly(v.y) + add;
    v.z = flog_poly(v.z) + add;
    v.w = flog_poly(v.w) + add;
    *p = v;
}

// ---------------- kernel 6: final log-likelihood ----------------
__global__ void ll_kernel(float* __restrict__ out, int out_size) {
    int lane = threadIdx.x;  // 32
    const float* last = out + (size_t)(TT - 1) * S;
    float v0 = last[lane], v1 = last[lane + 32], v2 = last[lane + 64], v3 = last[lane + 96];
    float m = fmaxf(fmaxf(v0, v1), fmaxf(v2, v3));
    for (int o = 16; o > 0; o >>= 1) m = fmaxf(m, __shfl_xor_sync(0xffffffffu, m, o));
    float s = __expf(v0 - m) + __expf(v1 - m) + __expf(v2 - m) + __expf(v3 - m);
    for (int o = 16; o > 0; o >>= 1) s += __shfl_xor_sync(0xffffffffu, s, o);
    if (lane == 0 && out_size > TT * S) out[(size_t)TT * S] = m + __logf(s);
}

// ---------------- launch ----------------
extern "C" void kernel_launch(void* const* d_in, const int* in_sizes, int n_in,
                              void* d_out, int out_size) {
    const float* x          = (const float*)d_in[0];
    const float* start_prob = (const float*)d_in[1];
    const float* trans      = (const float*)d_in[2];
    const float* means      = (const float*)d_in[3];
    const float* vars       = (const float*)d_in[4];
    float* out = (float*)d_out;

    prep_kernel<<<1, 128>>>(start_prob, trans, means, vars);
    logb_kernel<<<TT / 64, 128>>>(x);
    scan_kernel<<<CH, 256>>>(out);
    delta_local_kernel<<<CH - 1, 128>>>(out);
    delta_scan_kernel<<<1, 32>>>();
    size_t n4 = (size_t)TT * S / 4;
    post_kernel<<<(unsigned)((n4 + 255) / 256), 256>>>(out);
    ll_kernel<<<1, 32>>>(out, out_size);
}